// round 14
// baseline (speedup 1.0000x reference)
#include <cuda_runtime.h>
#include <math_constants.h>

// Reservoir2D: R13 + producer batch x8 + branchless erfinv.
// Grid 296 x 512 = 2 CTAs/SM, all co-resident.
//   CTAs [0,64): sim, 1 thread = 2 adjacent oscillators (ILP-2, bit-exact).
//   CTAs [64,296): threefry/erfinv noise producers, work stealing in
//                  4096-quad batches (8 sequential quads per thread).

#define BATCHN 64
#define NN     1024
#define NSTEP  1000
#define NOUT   10
#define LENTB  20
#define FEATS  (NN * LENTB)
#define ETOT   (BATCHN * NN)        // 65536 per step
#define CHSTEP 20
#define NCHUNK (NSTEP / CHSTEP)     // 50
#define NPROD  232
#define TOTAL_CTAS (BATCHN + NPROD) // 296 = 2*148
#define TPB    512
#define QPC    ((CHSTEP * ETOT) / 4)  // 327680 quads per chunk
#define BREP   8
#define BATCHQ (TPB * BREP)           // 4096 quads per steal-grab

__device__ float    g_noise[NSTEP * ETOT];   // 262 MB scratch
__device__ unsigned g_cnt[128];              // per-chunk completion counters
__device__ unsigned g_work[128];             // per-chunk steal counters

// ---- bit-exact division by small integer constant: q = fma(x,c1, x*c2) ----
__device__ __forceinline__ float divc(float x, float c1, float c2) {
    return fmaf(x, c1, x * c2);
}
#define DC(d) (float)(1.0/(d)), (float)(1.0/(d) - (double)(float)(1.0/(d)))

// ---------------- JAX threefry2x32 (exact) ----------------
__device__ __forceinline__ void tf2x32(unsigned k0, unsigned k1,
                                       unsigned x0, unsigned x1,
                                       unsigned& o0, unsigned& o1) {
    unsigned k2 = k0 ^ k1 ^ 0x1BD11BDAu;
    x0 += k0; x1 += k1;
#define TF_R(r) { x0 += x1; x1 = __funnelshift_l(x1, x1, (r)); x1 ^= x0; }
    TF_R(13) TF_R(15) TF_R(26) TF_R(6)
    x0 += k1; x1 += k2 + 1u;
    TF_R(17) TF_R(29) TF_R(16) TF_R(24)
    x0 += k2; x1 += k0 + 2u;
    TF_R(13) TF_R(15) TF_R(26) TF_R(6)
    x0 += k0; x1 += k1 + 3u;
    TF_R(17) TF_R(29) TF_R(16) TF_R(24)
    x0 += k1; x1 += k2 + 4u;
    TF_R(13) TF_R(15) TF_R(26) TF_R(6)
    x0 += k2; x1 += k0 + 5u;
#undef TF_R
    o0 = x0; o1 = x1;
}

// ---------------- XLA ErfInv32, branchless (bit-identical select) ----------------
__device__ __forceinline__ float erfinv_xla(float x) {
    float w = -log1pf(-x * x);
    // arm A: w < 5
    float wa = w - 2.5f;
    float pa = 2.81022636e-08f;
    pa = fmaf(pa, wa, 3.43273939e-07f);
    pa = fmaf(pa, wa, -3.5233877e-06f);
    pa = fmaf(pa, wa, -4.39150654e-06f);
    pa = fmaf(pa, wa, 0.00021858087f);
    pa = fmaf(pa, wa, -0.00125372503f);
    pa = fmaf(pa, wa, -0.00417768164f);
    pa = fmaf(pa, wa, 0.246640727f);
    pa = fmaf(pa, wa, 1.50140941f);
    // arm B: w >= 5
    float wb = sqrtf(w) - 3.0f;
    float pb = -0.000200214257f;
    pb = fmaf(pb, wb, 0.000100950558f);
    pb = fmaf(pb, wb, 0.00134934322f);
    pb = fmaf(pb, wb, -0.00367342844f);
    pb = fmaf(pb, wb, 0.00573950773f);
    pb = fmaf(pb, wb, -0.0076224613f);
    pb = fmaf(pb, wb, 0.00943887047f);
    pb = fmaf(pb, wb, 1.00167406f);
    pb = fmaf(pb, wb, 2.83297682f);
    float p = (w < 5.0f) ? pa : pb;
    return p * x;
}

__device__ __forceinline__ float bits_to_noise(unsigned bits) {
    const float U_LO   = -0.99999994039535522461f;
    const float SQRT2  = 1.41421353816986083984f;
    const float NSCALE = 0.001f * 3.1622776985168457f;
    float f = __uint_as_float((bits >> 9) | 0x3F800000u) - 1.0f;
    float u = fmaxf(f * 2.0f + U_LO, U_LO);
    return NSCALE * (SQRT2 * erfinv_xla(u));
}

// Quad of noise values for elements e0..e0+3, same step key.
__device__ __forceinline__ float4 noise_quad(unsigned k0, unsigned k1, unsigned e0) {
    unsigned k2 = k0 ^ k1 ^ 0x1BD11BDAu;
    unsigned a0 = k0, a1 = e0 + k1;
    unsigned b0 = k0, b1 = (e0 + 1u) + k1;
    unsigned c0 = k0, c1 = (e0 + 2u) + k1;
    unsigned d0 = k0, d1 = (e0 + 3u) + k1;
#define R4(r) { a0 += a1; b0 += b1; c0 += c1; d0 += d1; \
                a1 = __funnelshift_l(a1, a1, (r)); b1 = __funnelshift_l(b1, b1, (r)); \
                c1 = __funnelshift_l(c1, c1, (r)); d1 = __funnelshift_l(d1, d1, (r)); \
                a1 ^= a0; b1 ^= b0; c1 ^= c0; d1 ^= d0; }
#define INJ4(kx, ky, cnt) { unsigned kyc = (ky) + (cnt); \
                a0 += (kx); b0 += (kx); c0 += (kx); d0 += (kx); \
                a1 += kyc;  b1 += kyc;  c1 += kyc;  d1 += kyc; }
    R4(13) R4(15) R4(26) R4(6)  INJ4(k1, k2, 1u)
    R4(17) R4(29) R4(16) R4(24) INJ4(k2, k0, 2u)
    R4(13) R4(15) R4(26) R4(6)  INJ4(k0, k1, 3u)
    R4(17) R4(29) R4(16) R4(24) INJ4(k1, k2, 4u)
    R4(13) R4(15) R4(26) R4(6)  INJ4(k2, k0, 5u)
#undef R4
#undef INJ4
    float4 r;
    r.x = bits_to_noise(a0 ^ a1);
    r.y = bits_to_noise(b0 ^ b1);
    r.z = bits_to_noise(c0 ^ c1);
    r.w = bits_to_noise(d0 ^ d1);
    return r;
}

__device__ __forceinline__ unsigned ld_acq(const unsigned* p) {
    unsigned v;
    asm volatile("ld.acquire.gpu.global.b32 %0, [%1];" : "=r"(v) : "l"(p));
    return v;
}

__global__ void reset_cnt_kernel() {
    if (threadIdx.x < 128) { g_cnt[threadIdx.x] = 0u; g_work[threadIdx.x] = 0u; }
}

__global__ __launch_bounds__(TPB, 2)
void Reservoir2D_kernel(const float* __restrict__ xin,
                        const float* __restrict__ W,
                        const float* __restrict__ bias,
                        float* __restrict__ out) {
    __shared__ float Tsh[2][NN];        // sim only
    __shared__ float red[16 * NOUT];    // sim only
    __shared__ uint2 keys[NSTEP];       // producer only
    __shared__ unsigned sh_base;        // producer only

    const int n = threadIdx.x;
    const int b = blockIdx.x;

    if (b >= BATCHN) {
        // ====== NOISE PRODUCER (work-stealing, 4096-quad batches) ======
        for (int t = n; t < NSTEP; t += TPB) {
            unsigned o0, o1;
            tf2x32(0u, 1u, 0u, (unsigned)t, o0, o1);   // fold-like split of key(1)
            keys[t] = make_uint2(o0, o1);
        }
        __syncthreads();

        float4* __restrict__ g4 = reinterpret_cast<float4*>(g_noise);
        for (int c = 0; c < NCHUNK; ++c) {
            const int qbase = c * QPC;
            for (;;) {
                if (n == 0) sh_base = atomicAdd(&g_work[c], (unsigned)BATCHQ);
                __syncthreads();
                unsigned base = sh_base;
                __syncthreads();
                if (base >= (unsigned)QPC) break;
#pragma unroll
                for (int r = 0; r < BREP; ++r) {
                    unsigned qi = base + (unsigned)(r * TPB + n);
                    if (qi < (unsigned)QPC) {
                        int gq = qbase + (int)qi;
                        int t  = gq >> 14;                  // 16384 quads per step
                        unsigned e0 = (unsigned)((gq << 2) & (ETOT - 1));
                        uint2 kk = keys[t];
                        g4[gq] = noise_quad(kk.x, kk.y, e0);
                    }
                }
            }
            if (n == 0) {
                __threadfence();
                atomicAdd(&g_cnt[c], 1u);
            }
        }
        return;
    }

    // ===================== SIMULATION (ILP-2) =====================
    // thread n handles oscillators (i, jj) and (i, jj+1), jj even.
    const int i  = n >> 4;
    const int jj = (n & 15) << 1;
    const int rowm = (((i + 31) & 31) << 5);
    const int rowp = (((i + 1)  & 31) << 5);
    const int rowi = (i << 5);
    const int jm1 = (jj + 31) & 31;
    const int jp2 = (jj + 2)  & 31;
    const int e   = b * NN + rowi + jj;      // even -> float2-aligned

    const float Vd0 = 11.0f + 2.0f * xin[e];
    const float Vd1 = 11.0f + 2.0f * xin[e + 1];
    float v0 = 0.0f, v1 = 0.0f;
    float T0 = 325.0f, T1 = 325.0f;
    float pI0 = CUDART_INF_F, pI1 = CUDART_INF_F;
    int   cd0 = 0, cd1 = 0;
    unsigned m0 = 0, m1 = 0;
    unsigned binbit = 1u;
    int c50 = 50;

    const float LOG_R_INS = 4.6051702499389648f;   // f32(log(100))

    if (n == 0) { while (ld_acq(&g_cnt[0]) < NPROD) __nanosleep(64); }
    __syncthreads();
    const float2* __restrict__ nzp = reinterpret_cast<const float2*>(g_noise + e);
    float2 nz = __ldg(nzp);
    nzp += ETOT / 2;

    int p = 0;
    for (int t = 0; t < NSTEP; ++t) {
        *reinterpret_cast<float2*>(&Tsh[p][rowi + jj]) = make_float2(T0, T1);

        const int tn = t + 1;
        if (tn < NSTEP && (tn % CHSTEP) == 0) {
            const int c = tn / CHSTEP;
            if (n == 0) { while (ld_acq(&g_cnt[c]) < NPROD) __nanosleep(64); }
            __syncthreads();
        }
        float2 nz_next = make_float2(0.0f, 0.0f);
        if (tn < NSTEP) nz_next = __ldg(nzp);
        nzp += ETOT / 2;

        __syncthreads();
        const float* Ts = Tsh[p];
        float2 up = *reinterpret_cast<const float2*>(&Ts[rowm + jj]);
        float2 dn = *reinterpret_cast<const float2*>(&Ts[rowp + jj]);
        float  lf = Ts[rowi + jm1];
        float  rt = Ts[rowi + jp2];
        // exact ref order: ((xm + xp) + ym) + yp - 4T
        float lap0 = ((up.x + dn.x) + lf) + T1 - 4.0f * T0;
        float lap1 = ((up.y + dn.y) + T0) + rt - 4.0f * T1;

        // ---- device model x2 (bit-identical; constant divides via 2-FMA) ----
        float xs0 = divc(T0 - 340.0f, DC(5.0));
        float xs1 = divc(T1 - 340.0f, DC(5.0));
        float s0  = 1.0f / (1.0f + expf(-xs0));
        float s1  = 1.0f / (1.0f + expf(-xs1));
        float G0  = expf(-((1.0f - s0) * LOG_R_INS));
        float G1  = expf(-((1.0f - s1) * LOG_R_INS));
        float I0  = v0 * G0;
        float I1  = v1 * G1;

        float vn0 = v0 + divc(10.0f * (divc(Vd0 - v0, DC(12.0)) - I0), DC(100.0));
        float vn1 = v1 + divc(10.0f * (divc(Vd1 - v1, DC(12.0)) - I1), DC(100.0));
        float q0  = (v0 * I0 - (T0 - 325.0f)) + 0.02f * lap0;
        float q1  = (v1 * I1 - (T1 - 325.0f)) + 0.02f * lap1;
        float Tn0 = (T0 + divc(10.0f * q0, DC(1000.0))) + nz.x;
        float Tn1 = (T1 + divc(10.0f * q1, DC(1000.0))) + nz.y;

        // ---- rising-edge peak detection, refractory 101 ----
        bool pk0 = (I0 > 1.5f) && (pI0 <= 1.5f) && (cd0 <= 0);
        bool pk1 = (I1 > 1.5f) && (pI1 <= 1.5f) && (cd1 <= 0);
        if (pk0) { m0 |= binbit; cd0 = 101; } else { cd0 -= 1; }
        if (pk1) { m1 |= binbit; cd1 = 101; } else { cd1 -= 1; }
        if (--c50 == 0) { c50 = 50; binbit <<= 1; }

        pI0 = I0; pI1 = I1; v0 = vn0; v1 = vn1; T0 = Tn0; T1 = Tn1;
        nz = nz_next; p ^= 1;
    }

    // ---- readout ----
    float acc[NOUT];
#pragma unroll
    for (int o = 0; o < NOUT; ++o) acc[o] = 0.0f;
    const int f0 = (rowi + jj) * LENTB;
#pragma unroll
    for (int tb = 0; tb < LENTB; ++tb) {
        if ((m0 >> tb) & 1u) {
            const float* wp = W + (f0 + tb);
#pragma unroll
            for (int o = 0; o < NOUT; ++o) acc[o] += wp[o * FEATS];
        }
        if ((m1 >> tb) & 1u) {
            const float* wp = W + (f0 + LENTB + tb);
#pragma unroll
            for (int o = 0; o < NOUT; ++o) acc[o] += wp[o * FEATS];
        }
    }
#pragma unroll
    for (int o = 0; o < NOUT; ++o) {
        float a2 = acc[o];
#pragma unroll
        for (int sft = 16; sft > 0; sft >>= 1)
            a2 += __shfl_xor_sync(0xFFFFFFFFu, a2, sft);
        acc[o] = a2;
    }
    const int wid = n >> 5;
    if ((n & 31) == 0) {
#pragma unroll
        for (int o = 0; o < NOUT; ++o) red[wid * NOUT + o] = acc[o];
    }
    __syncthreads();

    if (n == 0) {
        float lg[NOUT];
#pragma unroll
        for (int o = 0; o < NOUT; ++o) {
            float sacc = bias[o];
            for (int w = 0; w < 16; ++w) sacc += red[w * NOUT + o];
            lg[o] = sacc;
        }
        float m = lg[0];
#pragma unroll
        for (int o = 1; o < NOUT; ++o) m = fmaxf(m, lg[o]);
        float se = 0.0f;
#pragma unroll
        for (int o = 0; o < NOUT; ++o) se += expf(lg[o] - m);
        float lse = logf(se);
#pragma unroll
        for (int o = 0; o < NOUT; ++o) out[b * NOUT + o] = (lg[o] - m) - lse;
    }
}

extern "C" void kernel_launch(void* const* d_in, const int* in_sizes, int n_in,
                              void* d_out, int out_size) {
    const float* x    = (const float*)d_in[0];
    const float* W    = (const float*)d_in[1];
    const float* bias = (const float*)d_in[2];
    float* out = (float*)d_out;
    reset_cnt_kernel<<<1, 128>>>();
    Reservoir2D_kernel<<<TOTAL_CTAS, TPB>>>(x, W, bias, out);
}

// round 15
// speedup vs baseline: 1.0009x; 1.0009x over previous
#include <cuda_runtime.h>
#include <math_constants.h>

// Reservoir2D: R13 config + producer batch x8 (branching erfinv restored).
// Grid 296 x 512 = 2 CTAs/SM, all co-resident.
//   CTAs [0,64): sim, 1 thread = 2 adjacent oscillators (ILP-2, bit-exact).
//   CTAs [64,296): threefry/erfinv noise producers, work stealing in
//                  4096-quad batches (8 sequential quads per thread).

#define BATCHN 64
#define NN     1024
#define NSTEP  1000
#define NOUT   10
#define LENTB  20
#define FEATS  (NN * LENTB)
#define ETOT   (BATCHN * NN)        // 65536 per step
#define CHSTEP 20
#define NCHUNK (NSTEP / CHSTEP)     // 50
#define NPROD  232
#define TOTAL_CTAS (BATCHN + NPROD) // 296 = 2*148
#define TPB    512
#define QPC    ((CHSTEP * ETOT) / 4)  // 327680 quads per chunk
#define BREP   8
#define BATCHQ (TPB * BREP)           // 4096 quads per steal-grab

__device__ float    g_noise[NSTEP * ETOT];   // 262 MB scratch
__device__ unsigned g_cnt[128];              // per-chunk completion counters
__device__ unsigned g_work[128];             // per-chunk steal counters

// ---- bit-exact division by small integer constant: q = fma(x,c1, x*c2) ----
__device__ __forceinline__ float divc(float x, float c1, float c2) {
    return fmaf(x, c1, x * c2);
}
#define DC(d) (float)(1.0/(d)), (float)(1.0/(d) - (double)(float)(1.0/(d)))

// ---------------- JAX threefry2x32 (exact) ----------------
__device__ __forceinline__ void tf2x32(unsigned k0, unsigned k1,
                                       unsigned x0, unsigned x1,
                                       unsigned& o0, unsigned& o1) {
    unsigned k2 = k0 ^ k1 ^ 0x1BD11BDAu;
    x0 += k0; x1 += k1;
#define TF_R(r) { x0 += x1; x1 = __funnelshift_l(x1, x1, (r)); x1 ^= x0; }
    TF_R(13) TF_R(15) TF_R(26) TF_R(6)
    x0 += k1; x1 += k2 + 1u;
    TF_R(17) TF_R(29) TF_R(16) TF_R(24)
    x0 += k2; x1 += k0 + 2u;
    TF_R(13) TF_R(15) TF_R(26) TF_R(6)
    x0 += k0; x1 += k1 + 3u;
    TF_R(17) TF_R(29) TF_R(16) TF_R(24)
    x0 += k1; x1 += k2 + 4u;
    TF_R(13) TF_R(15) TF_R(26) TF_R(6)
    x0 += k2; x1 += k0 + 5u;
#undef TF_R
    o0 = x0; o1 = x1;
}

// ---------------- XLA ErfInv32 (Giles polynomial, exact, branching) ----------------
__device__ __forceinline__ float erfinv_xla(float x) {
    float w = -log1pf(-x * x);
    float p;
    if (w < 5.0f) {
        w = w - 2.5f;
        p = 2.81022636e-08f;
        p = fmaf(p, w, 3.43273939e-07f);
        p = fmaf(p, w, -3.5233877e-06f);
        p = fmaf(p, w, -4.39150654e-06f);
        p = fmaf(p, w, 0.00021858087f);
        p = fmaf(p, w, -0.00125372503f);
        p = fmaf(p, w, -0.00417768164f);
        p = fmaf(p, w, 0.246640727f);
        p = fmaf(p, w, 1.50140941f);
    } else {
        w = sqrtf(w) - 3.0f;
        p = -0.000200214257f;
        p = fmaf(p, w, 0.000100950558f);
        p = fmaf(p, w, 0.00134934322f);
        p = fmaf(p, w, -0.00367342844f);
        p = fmaf(p, w, 0.00573950773f);
        p = fmaf(p, w, -0.0076224613f);
        p = fmaf(p, w, 0.00943887047f);
        p = fmaf(p, w, 1.00167406f);
        p = fmaf(p, w, 2.83297682f);
    }
    return p * x;
}

__device__ __forceinline__ float bits_to_noise(unsigned bits) {
    const float U_LO   = -0.99999994039535522461f;
    const float SQRT2  = 1.41421353816986083984f;
    const float NSCALE = 0.001f * 3.1622776985168457f;
    float f = __uint_as_float((bits >> 9) | 0x3F800000u) - 1.0f;
    float u = fmaxf(f * 2.0f + U_LO, U_LO);
    return NSCALE * (SQRT2 * erfinv_xla(u));
}

// Quad of noise values for elements e0..e0+3, same step key.
__device__ __forceinline__ float4 noise_quad(unsigned k0, unsigned k1, unsigned e0) {
    unsigned k2 = k0 ^ k1 ^ 0x1BD11BDAu;
    unsigned a0 = k0, a1 = e0 + k1;
    unsigned b0 = k0, b1 = (e0 + 1u) + k1;
    unsigned c0 = k0, c1 = (e0 + 2u) + k1;
    unsigned d0 = k0, d1 = (e0 + 3u) + k1;
#define R4(r) { a0 += a1; b0 += b1; c0 += c1; d0 += d1; \
                a1 = __funnelshift_l(a1, a1, (r)); b1 = __funnelshift_l(b1, b1, (r)); \
                c1 = __funnelshift_l(c1, c1, (r)); d1 = __funnelshift_l(d1, d1, (r)); \
                a1 ^= a0; b1 ^= b0; c1 ^= c0; d1 ^= d0; }
#define INJ4(kx, ky, cnt) { unsigned kyc = (ky) + (cnt); \
                a0 += (kx); b0 += (kx); c0 += (kx); d0 += (kx); \
                a1 += kyc;  b1 += kyc;  c1 += kyc;  d1 += kyc; }
    R4(13) R4(15) R4(26) R4(6)  INJ4(k1, k2, 1u)
    R4(17) R4(29) R4(16) R4(24) INJ4(k2, k0, 2u)
    R4(13) R4(15) R4(26) R4(6)  INJ4(k0, k1, 3u)
    R4(17) R4(29) R4(16) R4(24) INJ4(k1, k2, 4u)
    R4(13) R4(15) R4(26) R4(6)  INJ4(k2, k0, 5u)
#undef R4
#undef INJ4
    float4 r;
    r.x = bits_to_noise(a0 ^ a1);
    r.y = bits_to_noise(b0 ^ b1);
    r.z = bits_to_noise(c0 ^ c1);
    r.w = bits_to_noise(d0 ^ d1);
    return r;
}

__device__ __forceinline__ unsigned ld_acq(const unsigned* p) {
    unsigned v;
    asm volatile("ld.acquire.gpu.global.b32 %0, [%1];" : "=r"(v) : "l"(p));
    return v;
}

__global__ void reset_cnt_kernel() {
    if (threadIdx.x < 128) { g_cnt[threadIdx.x] = 0u; g_work[threadIdx.x] = 0u; }
}

__global__ __launch_bounds__(TPB, 2)
void Reservoir2D_kernel(const float* __restrict__ xin,
                        const float* __restrict__ W,
                        const float* __restrict__ bias,
                        float* __restrict__ out) {
    __shared__ float Tsh[2][NN];        // sim only
    __shared__ float red[16 * NOUT];    // sim only
    __shared__ uint2 keys[NSTEP];       // producer only
    __shared__ unsigned sh_base;        // producer only

    const int n = threadIdx.x;
    const int b = blockIdx.x;

    if (b >= BATCHN) {
        // ====== NOISE PRODUCER (work-stealing, 4096-quad batches) ======
        for (int t = n; t < NSTEP; t += TPB) {
            unsigned o0, o1;
            tf2x32(0u, 1u, 0u, (unsigned)t, o0, o1);   // fold-like split of key(1)
            keys[t] = make_uint2(o0, o1);
        }
        __syncthreads();

        float4* __restrict__ g4 = reinterpret_cast<float4*>(g_noise);
        for (int c = 0; c < NCHUNK; ++c) {
            const int qbase = c * QPC;
            for (;;) {
                if (n == 0) sh_base = atomicAdd(&g_work[c], (unsigned)BATCHQ);
                __syncthreads();
                unsigned base = sh_base;
                __syncthreads();
                if (base >= (unsigned)QPC) break;
#pragma unroll
                for (int r = 0; r < BREP; ++r) {
                    unsigned qi = base + (unsigned)(r * TPB + n);
                    if (qi < (unsigned)QPC) {
                        int gq = qbase + (int)qi;
                        int t  = gq >> 14;                  // 16384 quads per step
                        unsigned e0 = (unsigned)((gq << 2) & (ETOT - 1));
                        uint2 kk = keys[t];
                        g4[gq] = noise_quad(kk.x, kk.y, e0);
                    }
                }
            }
            if (n == 0) {
                __threadfence();
                atomicAdd(&g_cnt[c], 1u);
            }
        }
        return;
    }

    // ===================== SIMULATION (ILP-2) =====================
    // thread n handles oscillators (i, jj) and (i, jj+1), jj even.
    const int i  = n >> 4;
    const int jj = (n & 15) << 1;
    const int rowm = (((i + 31) & 31) << 5);
    const int rowp = (((i + 1)  & 31) << 5);
    const int rowi = (i << 5);
    const int jm1 = (jj + 31) & 31;
    const int jp2 = (jj + 2)  & 31;
    const int e   = b * NN + rowi + jj;      // even -> float2-aligned

    const float Vd0 = 11.0f + 2.0f * xin[e];
    const float Vd1 = 11.0f + 2.0f * xin[e + 1];
    float v0 = 0.0f, v1 = 0.0f;
    float T0 = 325.0f, T1 = 325.0f;
    float pI0 = CUDART_INF_F, pI1 = CUDART_INF_F;
    int   cd0 = 0, cd1 = 0;
    unsigned m0 = 0, m1 = 0;
    unsigned binbit = 1u;
    int c50 = 50;

    const float LOG_R_INS = 4.6051702499389648f;   // f32(log(100))

    if (n == 0) { while (ld_acq(&g_cnt[0]) < NPROD) __nanosleep(64); }
    __syncthreads();
    const float2* __restrict__ nzp = reinterpret_cast<const float2*>(g_noise + e);
    float2 nz = __ldg(nzp);
    nzp += ETOT / 2;

    int p = 0;
    for (int t = 0; t < NSTEP; ++t) {
        *reinterpret_cast<float2*>(&Tsh[p][rowi + jj]) = make_float2(T0, T1);

        const int tn = t + 1;
        if (tn < NSTEP && (tn % CHSTEP) == 0) {
            const int c = tn / CHSTEP;
            if (n == 0) { while (ld_acq(&g_cnt[c]) < NPROD) __nanosleep(64); }
            __syncthreads();
        }
        float2 nz_next = make_float2(0.0f, 0.0f);
        if (tn < NSTEP) nz_next = __ldg(nzp);
        nzp += ETOT / 2;

        __syncthreads();
        const float* Ts = Tsh[p];
        float2 up = *reinterpret_cast<const float2*>(&Ts[rowm + jj]);
        float2 dn = *reinterpret_cast<const float2*>(&Ts[rowp + jj]);
        float  lf = Ts[rowi + jm1];
        float  rt = Ts[rowi + jp2];
        // exact ref order: ((xm + xp) + ym) + yp - 4T
        float lap0 = ((up.x + dn.x) + lf) + T1 - 4.0f * T0;
        float lap1 = ((up.y + dn.y) + T0) + rt - 4.0f * T1;

        // ---- device model x2 (bit-identical; constant divides via 2-FMA) ----
        float xs0 = divc(T0 - 340.0f, DC(5.0));
        float xs1 = divc(T1 - 340.0f, DC(5.0));
        float s0  = 1.0f / (1.0f + expf(-xs0));
        float s1  = 1.0f / (1.0f + expf(-xs1));
        float G0  = expf(-((1.0f - s0) * LOG_R_INS));
        float G1  = expf(-((1.0f - s1) * LOG_R_INS));
        float I0  = v0 * G0;
        float I1  = v1 * G1;

        float vn0 = v0 + divc(10.0f * (divc(Vd0 - v0, DC(12.0)) - I0), DC(100.0));
        float vn1 = v1 + divc(10.0f * (divc(Vd1 - v1, DC(12.0)) - I1), DC(100.0));
        float q0  = (v0 * I0 - (T0 - 325.0f)) + 0.02f * lap0;
        float q1  = (v1 * I1 - (T1 - 325.0f)) + 0.02f * lap1;
        float Tn0 = (T0 + divc(10.0f * q0, DC(1000.0))) + nz.x;
        float Tn1 = (T1 + divc(10.0f * q1, DC(1000.0))) + nz.y;

        // ---- rising-edge peak detection, refractory 101 ----
        bool pk0 = (I0 > 1.5f) && (pI0 <= 1.5f) && (cd0 <= 0);
        bool pk1 = (I1 > 1.5f) && (pI1 <= 1.5f) && (cd1 <= 0);
        if (pk0) { m0 |= binbit; cd0 = 101; } else { cd0 -= 1; }
        if (pk1) { m1 |= binbit; cd1 = 101; } else { cd1 -= 1; }
        if (--c50 == 0) { c50 = 50; binbit <<= 1; }

        pI0 = I0; pI1 = I1; v0 = vn0; v1 = vn1; T0 = Tn0; T1 = Tn1;
        nz = nz_next; p ^= 1;
    }

    // ---- readout ----
    float acc[NOUT];
#pragma unroll
    for (int o = 0; o < NOUT; ++o) acc[o] = 0.0f;
    const int f0 = (rowi + jj) * LENTB;
#pragma unroll
    for (int tb = 0; tb < LENTB; ++tb) {
        if ((m0 >> tb) & 1u) {
            const float* wp = W + (f0 + tb);
#pragma unroll
            for (int o = 0; o < NOUT; ++o) acc[o] += wp[o * FEATS];
        }
        if ((m1 >> tb) & 1u) {
            const float* wp = W + (f0 + LENTB + tb);
#pragma unroll
            for (int o = 0; o < NOUT; ++o) acc[o] += wp[o * FEATS];
        }
    }
#pragma unroll
    for (int o = 0; o < NOUT; ++o) {
        float a2 = acc[o];
#pragma unroll
        for (int sft = 16; sft > 0; sft >>= 1)
            a2 += __shfl_xor_sync(0xFFFFFFFFu, a2, sft);
        acc[o] = a2;
    }
    const int wid = n >> 5;
    if ((n & 31) == 0) {
#pragma unroll
        for (int o = 0; o < NOUT; ++o) red[wid * NOUT + o] = acc[o];
    }
    __syncthreads();

    if (n == 0) {
        float lg[NOUT];
#pragma unroll
        for (int o = 0; o < NOUT; ++o) {
            float sacc = bias[o];
            for (int w = 0; w < 16; ++w) sacc += red[w * NOUT + o];
            lg[o] = sacc;
        }
        float m = lg[0];
#pragma unroll
        for (int o = 1; o < NOUT; ++o) m = fmaxf(m, lg[o]);
        float se = 0.0f;
#pragma unroll
        for (int o = 0; o < NOUT; ++o) se += expf(lg[o] - m);
        float lse = logf(se);
#pragma unroll
        for (int o = 0; o < NOUT; ++o) out[b * NOUT + o] = (lg[o] - m) - lse;
    }
}

extern "C" void kernel_launch(void* const* d_in, const int* in_sizes, int n_in,
                              void* d_out, int out_size) {
    const float* x    = (const float*)d_in[0];
    const float* W    = (const float*)d_in[1];
    const float* bias = (const float*)d_in[2];
    float* out = (float*)d_out;
    reset_cnt_kernel<<<1, 128>>>();
    Reservoir2D_kernel<<<TOTAL_CTAS, TPB>>>(x, W, bias, out);
}

// round 16
// speedup vs baseline: 1.1975x; 1.1964x over previous
#include <cuda_runtime.h>
#include <math_constants.h>

// Reservoir2D: R13 config (BREP=4, branching erfinv, CHSTEP=20) with
// quad-count chunk completion (sim unblocks when chunk DATA is done,
// not when all producer CTAs have checked in).
// Grid 296 x 512 = 2 CTAs/SM, all co-resident.
//   CTAs [0,64): sim, 1 thread = 2 adjacent oscillators (ILP-2, bit-exact).
//   CTAs [64,296): threefry/erfinv producers, stealing in 2048-quad batches.

#define BATCHN 64
#define NN     1024
#define NSTEP  1000
#define NOUT   10
#define LENTB  20
#define FEATS  (NN * LENTB)
#define ETOT   (BATCHN * NN)        // 65536 per step
#define CHSTEP 20
#define NCHUNK (NSTEP / CHSTEP)     // 50
#define NPROD  232
#define TOTAL_CTAS (BATCHN + NPROD) // 296 = 2*148
#define TPB    512
#define QPC    ((CHSTEP * ETOT) / 4)  // 327680 quads per chunk
#define BREP   4
#define BATCHQ (TPB * BREP)           // 2048 quads per steal-grab

__device__ float    g_noise[NSTEP * ETOT];   // 262 MB scratch
__device__ unsigned g_done[128];             // per-chunk produced-quad counters
__device__ unsigned g_work[128];             // per-chunk steal counters

// ---- bit-exact division by small integer constant: q = fma(x,c1, x*c2) ----
__device__ __forceinline__ float divc(float x, float c1, float c2) {
    return fmaf(x, c1, x * c2);
}
#define DC(d) (float)(1.0/(d)), (float)(1.0/(d) - (double)(float)(1.0/(d)))

// ---------------- JAX threefry2x32 (exact) ----------------
__device__ __forceinline__ void tf2x32(unsigned k0, unsigned k1,
                                       unsigned x0, unsigned x1,
                                       unsigned& o0, unsigned& o1) {
    unsigned k2 = k0 ^ k1 ^ 0x1BD11BDAu;
    x0 += k0; x1 += k1;
#define TF_R(r) { x0 += x1; x1 = __funnelshift_l(x1, x1, (r)); x1 ^= x0; }
    TF_R(13) TF_R(15) TF_R(26) TF_R(6)
    x0 += k1; x1 += k2 + 1u;
    TF_R(17) TF_R(29) TF_R(16) TF_R(24)
    x0 += k2; x1 += k0 + 2u;
    TF_R(13) TF_R(15) TF_R(26) TF_R(6)
    x0 += k0; x1 += k1 + 3u;
    TF_R(17) TF_R(29) TF_R(16) TF_R(24)
    x0 += k1; x1 += k2 + 4u;
    TF_R(13) TF_R(15) TF_R(26) TF_R(6)
    x0 += k2; x1 += k0 + 5u;
#undef TF_R
    o0 = x0; o1 = x1;
}

// ---------------- XLA ErfInv32 (Giles polynomial, exact, branching) ----------------
__device__ __forceinline__ float erfinv_xla(float x) {
    float w = -log1pf(-x * x);
    float p;
    if (w < 5.0f) {
        w = w - 2.5f;
        p = 2.81022636e-08f;
        p = fmaf(p, w, 3.43273939e-07f);
        p = fmaf(p, w, -3.5233877e-06f);
        p = fmaf(p, w, -4.39150654e-06f);
        p = fmaf(p, w, 0.00021858087f);
        p = fmaf(p, w, -0.00125372503f);
        p = fmaf(p, w, -0.00417768164f);
        p = fmaf(p, w, 0.246640727f);
        p = fmaf(p, w, 1.50140941f);
    } else {
        w = sqrtf(w) - 3.0f;
        p = -0.000200214257f;
        p = fmaf(p, w, 0.000100950558f);
        p = fmaf(p, w, 0.00134934322f);
        p = fmaf(p, w, -0.00367342844f);
        p = fmaf(p, w, 0.00573950773f);
        p = fmaf(p, w, -0.0076224613f);
        p = fmaf(p, w, 0.00943887047f);
        p = fmaf(p, w, 1.00167406f);
        p = fmaf(p, w, 2.83297682f);
    }
    return p * x;
}

__device__ __forceinline__ float bits_to_noise(unsigned bits) {
    const float U_LO   = -0.99999994039535522461f;
    const float SQRT2  = 1.41421353816986083984f;
    const float NSCALE = 0.001f * 3.1622776985168457f;
    float f = __uint_as_float((bits >> 9) | 0x3F800000u) - 1.0f;
    float u = fmaxf(f * 2.0f + U_LO, U_LO);
    return NSCALE * (SQRT2 * erfinv_xla(u));
}

// Quad of noise values for elements e0..e0+3, same step key.
__device__ __forceinline__ float4 noise_quad(unsigned k0, unsigned k1, unsigned e0) {
    unsigned k2 = k0 ^ k1 ^ 0x1BD11BDAu;
    unsigned a0 = k0, a1 = e0 + k1;
    unsigned b0 = k0, b1 = (e0 + 1u) + k1;
    unsigned c0 = k0, c1 = (e0 + 2u) + k1;
    unsigned d0 = k0, d1 = (e0 + 3u) + k1;
#define R4(r) { a0 += a1; b0 += b1; c0 += c1; d0 += d1; \
                a1 = __funnelshift_l(a1, a1, (r)); b1 = __funnelshift_l(b1, b1, (r)); \
                c1 = __funnelshift_l(c1, c1, (r)); d1 = __funnelshift_l(d1, d1, (r)); \
                a1 ^= a0; b1 ^= b0; c1 ^= c0; d1 ^= d0; }
#define INJ4(kx, ky, cnt) { unsigned kyc = (ky) + (cnt); \
                a0 += (kx); b0 += (kx); c0 += (kx); d0 += (kx); \
                a1 += kyc;  b1 += kyc;  c1 += kyc;  d1 += kyc; }
    R4(13) R4(15) R4(26) R4(6)  INJ4(k1, k2, 1u)
    R4(17) R4(29) R4(16) R4(24) INJ4(k2, k0, 2u)
    R4(13) R4(15) R4(26) R4(6)  INJ4(k0, k1, 3u)
    R4(17) R4(29) R4(16) R4(24) INJ4(k1, k2, 4u)
    R4(13) R4(15) R4(26) R4(6)  INJ4(k2, k0, 5u)
#undef R4
#undef INJ4
    float4 r;
    r.x = bits_to_noise(a0 ^ a1);
    r.y = bits_to_noise(b0 ^ b1);
    r.z = bits_to_noise(c0 ^ c1);
    r.w = bits_to_noise(d0 ^ d1);
    return r;
}

__device__ __forceinline__ unsigned ld_acq(const unsigned* p) {
    unsigned v;
    asm volatile("ld.acquire.gpu.global.b32 %0, [%1];" : "=r"(v) : "l"(p));
    return v;
}

__global__ void reset_cnt_kernel() {
    if (threadIdx.x < 128) { g_done[threadIdx.x] = 0u; g_work[threadIdx.x] = 0u; }
}

__global__ __launch_bounds__(TPB, 2)
void Reservoir2D_kernel(const float* __restrict__ xin,
                        const float* __restrict__ W,
                        const float* __restrict__ bias,
                        float* __restrict__ out) {
    __shared__ float Tsh[2][NN];        // sim only
    __shared__ float red[16 * NOUT];    // sim only
    __shared__ uint2 keys[NSTEP];       // producer only
    __shared__ unsigned sh_base;        // producer only

    const int n = threadIdx.x;
    const int b = blockIdx.x;

    if (b >= BATCHN) {
        // ====== NOISE PRODUCER (stealing, 2048-quad grabs, quad-count done) ======
        for (int t = n; t < NSTEP; t += TPB) {
            unsigned o0, o1;
            tf2x32(0u, 1u, 0u, (unsigned)t, o0, o1);   // fold-like split of key(1)
            keys[t] = make_uint2(o0, o1);
        }
        __syncthreads();

        float4* __restrict__ g4 = reinterpret_cast<float4*>(g_noise);
        for (int c = 0; c < NCHUNK; ++c) {
            const int qbase = c * QPC;
            for (;;) {
                if (n == 0) sh_base = atomicAdd(&g_work[c], (unsigned)BATCHQ);
                __syncthreads();
                unsigned base = sh_base;
                __syncthreads();
                if (base >= (unsigned)QPC) break;
#pragma unroll
                for (int r = 0; r < BREP; ++r) {
                    unsigned qi = base + (unsigned)(r * TPB + n);
                    if (qi < (unsigned)QPC) {
                        int gq = qbase + (int)qi;
                        int t  = gq >> 14;                  // 16384 quads per step
                        unsigned e0 = (unsigned)((gq << 2) & (ETOT - 1));
                        uint2 kk = keys[t];
                        g4[gq] = noise_quad(kk.x, kk.y, e0);
                    }
                }
                __syncthreads();                            // all grab stores issued
                if (n == 0) {
                    unsigned cnt = min((unsigned)BATCHQ, (unsigned)QPC - base);
                    __threadfence();
                    atomicAdd(&g_done[c], cnt);
                }
            }
        }
        return;
    }

    // ===================== SIMULATION (ILP-2) =====================
    // thread n handles oscillators (i, jj) and (i, jj+1), jj even.
    const int i  = n >> 4;
    const int jj = (n & 15) << 1;
    const int rowm = (((i + 31) & 31) << 5);
    const int rowp = (((i + 1)  & 31) << 5);
    const int rowi = (i << 5);
    const int jm1 = (jj + 31) & 31;
    const int jp2 = (jj + 2)  & 31;
    const int e   = b * NN + rowi + jj;      // even -> float2-aligned

    const float Vd0 = 11.0f + 2.0f * xin[e];
    const float Vd1 = 11.0f + 2.0f * xin[e + 1];
    float v0 = 0.0f, v1 = 0.0f;
    float T0 = 325.0f, T1 = 325.0f;
    float pI0 = CUDART_INF_F, pI1 = CUDART_INF_F;
    int   cd0 = 0, cd1 = 0;
    unsigned m0 = 0, m1 = 0;
    unsigned binbit = 1u;
    int c50 = 50;

    const float LOG_R_INS = 4.6051702499389648f;   // f32(log(100))

    if (n == 0) { while (ld_acq(&g_done[0]) < (unsigned)QPC) __nanosleep(64); }
    __syncthreads();
    const float2* __restrict__ nzp = reinterpret_cast<const float2*>(g_noise + e);
    float2 nz = __ldg(nzp);
    nzp += ETOT / 2;

    int p = 0;
    for (int t = 0; t < NSTEP; ++t) {
        *reinterpret_cast<float2*>(&Tsh[p][rowi + jj]) = make_float2(T0, T1);

        const int tn = t + 1;
        if (tn < NSTEP && (tn % CHSTEP) == 0) {
            const int c = tn / CHSTEP;
            if (n == 0) { while (ld_acq(&g_done[c]) < (unsigned)QPC) __nanosleep(64); }
            __syncthreads();
        }
        float2 nz_next = make_float2(0.0f, 0.0f);
        if (tn < NSTEP) nz_next = __ldg(nzp);
        nzp += ETOT / 2;

        __syncthreads();
        const float* Ts = Tsh[p];
        float2 up = *reinterpret_cast<const float2*>(&Ts[rowm + jj]);
        float2 dn = *reinterpret_cast<const float2*>(&Ts[rowp + jj]);
        float  lf = Ts[rowi + jm1];
        float  rt = Ts[rowi + jp2];
        // exact ref order: ((xm + xp) + ym) + yp - 4T
        float lap0 = ((up.x + dn.x) + lf) + T1 - 4.0f * T0;
        float lap1 = ((up.y + dn.y) + T0) + rt - 4.0f * T1;

        // ---- device model x2 (bit-identical; constant divides via 2-FMA) ----
        float xs0 = divc(T0 - 340.0f, DC(5.0));
        float xs1 = divc(T1 - 340.0f, DC(5.0));
        float s0  = 1.0f / (1.0f + expf(-xs0));
        float s1  = 1.0f / (1.0f + expf(-xs1));
        float G0  = expf(-((1.0f - s0) * LOG_R_INS));
        float G1  = expf(-((1.0f - s1) * LOG_R_INS));
        float I0  = v0 * G0;
        float I1  = v1 * G1;

        float vn0 = v0 + divc(10.0f * (divc(Vd0 - v0, DC(12.0)) - I0), DC(100.0));
        float vn1 = v1 + divc(10.0f * (divc(Vd1 - v1, DC(12.0)) - I1), DC(100.0));
        float q0  = (v0 * I0 - (T0 - 325.0f)) + 0.02f * lap0;
        float q1  = (v1 * I1 - (T1 - 325.0f)) + 0.02f * lap1;
        float Tn0 = (T0 + divc(10.0f * q0, DC(1000.0))) + nz.x;
        float Tn1 = (T1 + divc(10.0f * q1, DC(1000.0))) + nz.y;

        // ---- rising-edge peak detection, refractory 101 ----
        bool pk0 = (I0 > 1.5f) && (pI0 <= 1.5f) && (cd0 <= 0);
        bool pk1 = (I1 > 1.5f) && (pI1 <= 1.5f) && (cd1 <= 0);
        if (pk0) { m0 |= binbit; cd0 = 101; } else { cd0 -= 1; }
        if (pk1) { m1 |= binbit; cd1 = 101; } else { cd1 -= 1; }
        if (--c50 == 0) { c50 = 50; binbit <<= 1; }

        pI0 = I0; pI1 = I1; v0 = vn0; v1 = vn1; T0 = Tn0; T1 = Tn1;
        nz = nz_next; p ^= 1;
    }

    // ---- readout ----
    float acc[NOUT];
#pragma unroll
    for (int o = 0; o < NOUT; ++o) acc[o] = 0.0f;
    const int f0 = (rowi + jj) * LENTB;
#pragma unroll
    for (int tb = 0; tb < LENTB; ++tb) {
        if ((m0 >> tb) & 1u) {
            const float* wp = W + (f0 + tb);
#pragma unroll
            for (int o = 0; o < NOUT; ++o) acc[o] += wp[o * FEATS];
        }
        if ((m1 >> tb) & 1u) {
            const float* wp = W + (f0 + LENTB + tb);
#pragma unroll
            for (int o = 0; o < NOUT; ++o) acc[o] += wp[o * FEATS];
        }
    }
#pragma unroll
    for (int o = 0; o < NOUT; ++o) {
        float a2 = acc[o];
#pragma unroll
        for (int sft = 16; sft > 0; sft >>= 1)
            a2 += __shfl_xor_sync(0xFFFFFFFFu, a2, sft);
        acc[o] = a2;
    }
    const int wid = n >> 5;
    if ((n & 31) == 0) {
#pragma unroll
        for (int o = 0; o < NOUT; ++o) red[wid * NOUT + o] = acc[o];
    }
    __syncthreads();

    if (n == 0) {
        float lg[NOUT];
#pragma unroll
        for (int o = 0; o < NOUT; ++o) {
            float sacc = bias[o];
            for (int w = 0; w < 16; ++w) sacc += red[w * NOUT + o];
            lg[o] = sacc;
        }
        float m = lg[0];
#pragma unroll
        for (int o = 1; o < NOUT; ++o) m = fmaxf(m, lg[o]);
        float se = 0.0f;
#pragma unroll
        for (int o = 0; o < NOUT; ++o) se += expf(lg[o] - m);
        float lse = logf(se);
#pragma unroll
        for (int o = 0; o < NOUT; ++o) out[b * NOUT + o] = (lg[o] - m) - lse;
    }
}

extern "C" void kernel_launch(void* const* d_in, const int* in_sizes, int n_in,
                              void* d_out, int out_size) {
    const float* x    = (const float*)d_in[0];
    const float* W    = (const float*)d_in[1];
    const float* bias = (const float*)d_in[2];
    float* out = (float*)d_out;
    reset_cnt_kernel<<<1, 128>>>();
    Reservoir2D_kernel<<<TOTAL_CTAS, TPB>>>(x, W, bias, out);
}